// round 14
// baseline (speedup 1.0000x reference)
#include <cuda_runtime.h>
#include <cuda_fp16.h>
#include <cstdint>
#include <cmath>

#define B_ 128
#define T_ 512
#define I_ 256
#define H_ 512
#define RCTAS 128
#define GRPSZ 32          // CTAs per barrier group (one per b-slice)

// ---- static device scratch ----
__device__ float    g_xproj[(size_t)4 * T_ * B_ * H_];  // [g][t][b][h]
__device__ __half   g_hH[2][B_][H_];                    // h fp16 [buf][b][h]
__device__ unsigned g_cnt[4][32];                       // per-group barrier counter
__device__ unsigned g_sns[4][32];                       // per-group barrier sense (persists)

// ---- packed fp32x2 (projection kernel) ----
__device__ __forceinline__ void fma2(unsigned long long& d,
                                     unsigned long long a,
                                     unsigned long long b) {
    asm("fma.rn.f32x2 %0, %1, %2, %0;" : "+l"(d) : "l"(a), "l"(b));
}
__device__ __forceinline__ float lo32(unsigned long long v) {
    return __uint_as_float((unsigned)(v & 0xffffffffull));
}
__device__ __forceinline__ float hi32(unsigned long long v) {
    return __uint_as_float((unsigned)(v >> 32));
}
__device__ __forceinline__ float rcpa(float x) {
    float r;
    asm("rcp.approx.f32 %0, %1;" : "=f"(r) : "f"(x));
    return r;
}
// rational tanh p/q (Eigen coefficients, float-accurate)
__device__ __forceinline__ void tanh_pq(float x, float& p, float& q) {
    x = fminf(fmaxf(x, -7.90531110763549805f), 7.90531110763549805f);
    float x2 = x * x;
    float pp = fmaf(x2, -2.76076847742355e-16f, 2.00018790482477e-13f);
    pp = fmaf(pp, x2, -8.60467152213735e-11f);
    pp = fmaf(pp, x2, 5.12229709037114e-08f);
    pp = fmaf(pp, x2, 1.48572235717979e-05f);
    pp = fmaf(pp, x2, 6.37261928875436e-04f);
    pp = fmaf(pp, x2, 4.89352455891786e-03f);
    p = pp * x;
    float qq = fmaf(x2, 1.19825839466702e-06f, 1.18534705686654e-04f);
    qq = fmaf(qq, x2, 2.26843463243900e-03f);
    q = fmaf(qq, x2, 4.89352518554385e-03f);
}
__device__ __forceinline__ void div4(const float* p, const float* q, float* o) {
    float q01 = q[0] * q[1], q23 = q[2] * q[3];
    float r   = rcpa(q01 * q23);
    float r01 = q23 * r, r23 = q01 * r;
    o[0] = p[0] * (q[1] * r01);
    o[1] = p[1] * (q[0] * r01);
    o[2] = p[2] * (q[3] * r23);
    o[3] = p[3] * (q[2] * r23);
}

// ---- warp MMA helpers ----
__device__ __forceinline__ void ldsm4(uint32_t& r0, uint32_t& r1, uint32_t& r2,
                                      uint32_t& r3, uint32_t addr) {
    asm volatile("ldmatrix.sync.aligned.m8n8.x4.shared.b16 {%0,%1,%2,%3}, [%4];"
                 : "=r"(r0), "=r"(r1), "=r"(r2), "=r"(r3) : "r"(addr));
}
__device__ __forceinline__ void ldsm2(uint32_t& r0, uint32_t& r1, uint32_t addr) {
    asm volatile("ldmatrix.sync.aligned.m8n8.x2.shared.b16 {%0,%1}, [%2];"
                 : "=r"(r0), "=r"(r1) : "r"(addr));
}
__device__ __forceinline__ void mma16816(float* c, uint32_t a0, uint32_t a1,
                                         uint32_t a2, uint32_t a3,
                                         uint32_t b0, uint32_t b1) {
    asm volatile(
        "mma.sync.aligned.m16n8k16.row.col.f32.f16.f16.f32 "
        "{%0,%1,%2,%3}, {%4,%5,%6,%7}, {%8,%9}, {%0,%1,%2,%3};"
        : "+f"(c[0]), "+f"(c[1]), "+f"(c[2]), "+f"(c[3])
        : "r"(a0), "r"(a1), "r"(a2), "r"(a3), "r"(b0), "r"(b1));
}

// ---------------------------------------------------------------------------
// projection GEMM (proven R6-R12): g_xproj[g][t][b][h] = x.W_g^T + b_g
// ---------------------------------------------------------------------------
__global__ __launch_bounds__(128) void lstm_proj(
    const float* __restrict__ x,
    const float* __restrict__ Wz, const float* __restrict__ Ws,
    const float* __restrict__ Wf, const float* __restrict__ Wo,
    const float* __restrict__ bz, const float* __restrict__ bs,
    const float* __restrict__ bf, const float* __restrict__ bo)
{
    __shared__ __align__(16) float2 As2[32][64];
    __shared__ __align__(16) float  Bs[32][64];

    const int tid = threadIdx.x;
    const int r0  = blockIdx.x * 64;
    const int n0  = blockIdx.y * 64;
    const int g   = n0 >> 9;
    const int h0  = n0 & 511;

    const float* W    = (g == 0) ? Wz : (g == 1) ? Ws : (g == 2) ? Wf : Wo;
    const float* bias = (g == 0) ? bz : (g == 1) ? bs : (g == 2) ? bf : bo;

    const int tn = tid & 7;
    const int tm = tid >> 3;
    const int lm = tid & 63;
    const int qb = (tid >> 6) * 4;
    const float* xr = x + (size_t)(r0 + lm) * I_;
    const float* wr = W + (size_t)(h0 + lm) * I_;

    unsigned long long acc[4][4];
#pragma unroll
    for (int i = 0; i < 4; i++)
#pragma unroll
        for (int j = 0; j < 4; j++) acc[i][j] = 0ull;

    float4 pa[4], pw[4];
#pragma unroll
    for (int i = 0; i < 4; i++) {
        pa[i] = *(const float4*)(xr + (qb + i) * 4);
        pw[i] = *(const float4*)(wr + (qb + i) * 4);
    }

    for (int kt = 0; kt < I_ / 32; kt++) {
#pragma unroll
        for (int i = 0; i < 4; i++) {
            int q = qb + i;
            As2[q * 4 + 0][lm] = make_float2(pa[i].x, pa[i].x);
            As2[q * 4 + 1][lm] = make_float2(pa[i].y, pa[i].y);
            As2[q * 4 + 2][lm] = make_float2(pa[i].z, pa[i].z);
            As2[q * 4 + 3][lm] = make_float2(pa[i].w, pa[i].w);
            Bs[q * 4 + 0][lm] = pw[i].x;
            Bs[q * 4 + 1][lm] = pw[i].y;
            Bs[q * 4 + 2][lm] = pw[i].z;
            Bs[q * 4 + 3][lm] = pw[i].w;
        }
        __syncthreads();
        if (kt + 1 < I_ / 32) {
            int k0 = (kt + 1) * 32;
#pragma unroll
            for (int i = 0; i < 4; i++) {
                pa[i] = *(const float4*)(xr + k0 + (qb + i) * 4);
                pw[i] = *(const float4*)(wr + k0 + (qb + i) * 4);
            }
        }
#pragma unroll
        for (int kk = 0; kk < 32; kk++) {
            ulonglong2 a01 = *(const ulonglong2*)&As2[kk][tm * 4];
            ulonglong2 a23 = *(const ulonglong2*)&As2[kk][tm * 4 + 2];
            ulonglong2 b01 = *(const ulonglong2*)&Bs[kk][tn * 8];
            ulonglong2 b23 = *(const ulonglong2*)&Bs[kk][tn * 8 + 4];
            fma2(acc[0][0], a01.x, b01.x); fma2(acc[0][1], a01.x, b01.y);
            fma2(acc[0][2], a01.x, b23.x); fma2(acc[0][3], a01.x, b23.y);
            fma2(acc[1][0], a01.y, b01.x); fma2(acc[1][1], a01.y, b01.y);
            fma2(acc[1][2], a01.y, b23.x); fma2(acc[1][3], a01.y, b23.y);
            fma2(acc[2][0], a23.x, b01.x); fma2(acc[2][1], a23.x, b01.y);
            fma2(acc[2][2], a23.x, b23.x); fma2(acc[2][3], a23.x, b23.y);
            fma2(acc[3][0], a23.y, b01.x); fma2(acc[3][1], a23.y, b01.y);
            fma2(acc[3][2], a23.y, b23.x); fma2(acc[3][3], a23.y, b23.y);
        }
        __syncthreads();
    }

    float bv[8];
#pragma unroll
    for (int j = 0; j < 8; j++) bv[j] = bias[h0 + tn * 8 + j];
#pragma unroll
    for (int i = 0; i < 4; i++) {
        int r  = r0 + tm * 4 + i;
        int bb = r >> 9;
        int tt = r & 511;
        float* orow = g_xproj + (((size_t)g * T_ + tt) * B_ + bb) * H_ + h0 + tn * 8;
#pragma unroll
        for (int jp = 0; jp < 4; jp++) {
            float2 v = make_float2(lo32(acc[i][jp]) + bv[jp * 2],
                                   hi32(acc[i][jp]) + bv[jp * 2 + 1]);
            *(float2*)(orow + jp * 2) = v;
        }
    }
}

// ---------------------------------------------------------------------------
// persistent HMMA recurrence. 128 CTAs x 256 thr, warp = (gate, n-half).
// CTA tile: M=64 (4g x 16h) x N=32 batch x K=512.
// Per warp: m16 x n16 x K512 (2 ldsm4 A + 2 ldsm2 B + 4 mma per k16).
// A = R hi/lo f16 smem-resident 128KB; B = h f16 staged per step 32KB.
// xproj for t+1 prefetched into regs BEFORE the inter-CTA barrier spin.
// ---------------------------------------------------------------------------
__global__ __launch_bounds__(256, 1) void lstm_recur(
    const float* __restrict__ Rz, const float* __restrict__ Rs_,
    const float* __restrict__ Rf, const float* __restrict__ Ro,
    float* __restrict__ out)
{
    extern __shared__ char sm[];
    char*  smA  = sm;                       // 131072 B
    char*  smB  = sm + 131072;              // 32768 B
    float* actp = (float*)(sm + 163840);    // [64][33] floats
    const uint32_t smem_base = (uint32_t)__cvta_generic_to_shared(sm);
    const uint32_t SM_A = smem_base;
    const uint32_t SM_B = smem_base + 131072;

    const int tid = threadIdx.x;
    const int w   = tid >> 5;
    const int l   = tid & 31;
    const int g   = w >> 1;            // gate
    const int p   = w & 1;             // n-half (0: n 0-15, 1: n 16-31)
    const int mt  = blockIdx.x >> 2;   // 32 h-tiles
    const int nt  = blockIdx.x & 3;    // 4 b-tiles
    const int h0  = mt * 16;
    const int b0  = nt * 32;

    // barrier sense (self-relative, persists across graph replays)
    unsigned s0 = 0;
    if (tid == 0) s0 = *(volatile unsigned*)&g_sns[nt][0];

    // ---- setup: A rows 0..63 = hi(f16 R), rows 64..127 = lo(f16 residual) ----
    {
        const int m  = tid & 63;            // row = gate*16 + hr
        const int kh = (tid >> 6) * 128;    // k quarter
        const int gg = m >> 4, hr = m & 15;
        const float* Rp = ((gg == 0) ? Rz : (gg == 1) ? Rs_ : (gg == 2) ? Rf : Ro)
                        + (size_t)(h0 + hr) * H_ + kh;
        char* rowHi = smA + m * 1024;
        char* rowLo = smA + (64 + m) * 1024;
        const int sx = m & 7;
#pragma unroll 8
        for (int k = 0; k < 128; k += 2) {
            float2 v = *(const float2*)(Rp + k);
            __half hv0 = __float2half(v.x);
            __half hv1 = __float2half(v.y);
            float r0 = v.x - __half2float(hv0);
            float r1 = v.y - __half2float(hv1);
            uint32_t hi = (uint32_t)__half_as_ushort(hv0)
                        | ((uint32_t)__half_as_ushort(hv1) << 16);
            uint32_t lo = (uint32_t)__half_as_ushort(__float2half(r0))
                        | ((uint32_t)__half_as_ushort(__float2half(r1)) << 16);
            int byte  = (kh + k) * 2;
            int chunk = byte >> 4;
            int off   = ((chunk ^ sx) << 4) + (byte & 15);
            *(uint32_t*)(rowHi + off) = hi;
            *(uint32_t*)(rowLo + off) = lo;
        }
    }
    __syncthreads();

    // ldmatrix lane-invariant addressing (verbatim from passing R12 layout)
    const uint32_t aRow  = (uint32_t)(g * 16 + (l & 15));
    const uint32_t aBase = SM_A + aRow * 1024u;
    const uint32_t aXor  = aRow & 7;
    const uint32_t aKl   = (uint32_t)(l >> 4);        // 0/1 (k octet)
    const uint32_t bRowL = (uint32_t)(l & 7);
    const uint32_t bKl   = (uint32_t)((l >> 3) & 1);
    const uint32_t bBase = SM_B + bRowL * 1024u;

    // epilogue identity (mma accumulator layout)
    const int erow = l >> 2;            // m rows erow, erow+8
    const int ecol = (l & 3) * 2;

    // combine identity: 2 cells (b = tid&31, h = h0 + hgrp*2, +1)
    const int hgrp = tid >> 5;          // 0..7
    const int cbn  = tid & 31;
    float creg[2] = {0, 0}, hsum[2] = {0, 0};

    // B staging role: 8 x 16B chunks per thread
    const int srow = tid >> 3;          // 0..31
    const int sc0  = (tid & 7) * 8;
    const int sx2  = srow & 7;

    // preload xproj for t=0 (warp covers gate g, n tiles 2p, 2p+1)
    float xv[2][4];
    {
        const float* xb = g_xproj + (((size_t)g * T_ + 0) * B_ + b0) * H_ + h0;
#pragma unroll
        for (int j = 0; j < 2; j++) {
            int n0c = (2 * p + j) * 8 + ecol;
            xv[j][0] = xb[(size_t)(n0c)     * H_ + erow];
            xv[j][1] = xb[(size_t)(n0c + 1) * H_ + erow];
            xv[j][2] = xb[(size_t)(n0c)     * H_ + erow + 8];
            xv[j][3] = xb[(size_t)(n0c + 1) * H_ + erow + 8];
        }
    }

    for (int t = 0; t < T_; t++) {
        float cacc[2][4];
#pragma unroll
        for (int i = 0; i < 2; i++)
#pragma unroll
            for (int j = 0; j < 4; j++) cacc[i][j] = 0.0f;

        if (t > 0) {
            // ---- stage B: g_hH[t&1][b0+row][k] -> swizzled smem ----
            {
                const char* gsrc = (const char*)&g_hH[t & 1][b0 + srow][0];
                char* sdst = smB + srow * 1024;
#pragma unroll
                for (int i = 0; i < 8; i++) {
                    int c = sc0 + i;
                    uint4 v = *(const uint4*)(gsrc + c * 16);
                    *(uint4*)(sdst + ((c ^ sx2) << 4)) = v;
                }
            }
            __syncthreads();

            // ---- GEMM: warp's D[16 m][16 n] += (A_hi + A_lo) . B^T ----
#pragma unroll 4
            for (int ks = 0; ks < 32; ks++) {
                uint32_t aOff = ((((uint32_t)(ks * 2) + aKl) ^ aXor) << 4);
                uint32_t ah0, ah1, ah2, ah3, al0, al1, al2, al3;
                ldsm4(ah0, ah1, ah2, ah3, aBase + aOff);
                ldsm4(al0, al1, al2, al3, aBase + 65536u + aOff);
                uint32_t bOff = ((((uint32_t)(ks * 2) + bKl) ^ bRowL) << 4);
                uint32_t bf0[2], bf1[2];
#pragma unroll
                for (int j = 0; j < 2; j++)
                    ldsm2(bf0[j], bf1[j], bBase + (2 * p + j) * 8192u + bOff);
#pragma unroll
                for (int j = 0; j < 2; j++) {
                    mma16816(cacc[j], ah0, ah1, ah2, ah3, bf0[j], bf1[j]);
                    mma16816(cacc[j], al0, al1, al2, al3, bf0[j], bf1[j]);
                }
            }
        }

        // ---- epilogue: 8 pre-acts -> rational tanh/sigmoid -> act smem ----
        {
            const bool  isz = (g == 0);
            const float s1  = isz ? 1.0f : 0.5f;
            const float scm = isz ? 1.0f : 0.5f;
            const float sca = isz ? 0.0f : 0.5f;
#pragma unroll
            for (int j = 0; j < 2; j++) {
                float pn[4], qn[4], av[4];
#pragma unroll
                for (int q4 = 0; q4 < 4; q4++) {
                    float v = (cacc[j][q4] + xv[j][q4]) * s1;
                    tanh_pq(v, pn[q4], qn[q4]);
                }
                div4(pn, qn, av);
#pragma unroll
                for (int q4 = 0; q4 < 4; q4++) av[q4] = fmaf(av[q4], scm, sca);
                int n = (2 * p + j) * 8 + ecol;
                actp[((erow)     * 4 + g) * 33 + n]     = av[0];
                actp[((erow)     * 4 + g) * 33 + n + 1] = av[1];
                actp[((erow + 8) * 4 + g) * 33 + n]     = av[2];
                actp[((erow + 8) * 4 + g) * 33 + n + 1] = av[3];
            }
        }
        __syncthreads();

        // ---- combine: 2 cells; c,h update; store h f16; accumulate sum ----
        {
            float pn[2], qn[2], ov[2];
#pragma unroll
            for (int j = 0; j < 2; j++) {
                int r4 = (hgrp * 2 + j) * 4;
                float z = actp[(r4 + 0) * 33 + cbn];
                float s = actp[(r4 + 1) * 33 + cbn];
                float f = actp[(r4 + 2) * 33 + cbn];
                ov[j]   = actp[(r4 + 3) * 33 + cbn];
                float c = fmaf(s, z, f * creg[j]);
                creg[j] = c;
                tanh_pq(c, pn[j], qn[j]);
            }
            float r  = rcpa(qn[0] * qn[1]);
            float t0 = pn[0] * (qn[1] * r);
            float t1 = pn[1] * (qn[0] * r);
            if (t < T_ - 1) {
                float hn0 = ov[0] * t0;
                float hn1 = ov[1] * t1;
                hsum[0] += hn0; hsum[1] += hn1;
                uint32_t pkt = (uint32_t)__half_as_ushort(__float2half(hn0))
                             | ((uint32_t)__half_as_ushort(__float2half(hn1)) << 16);
                *(uint32_t*)&g_hH[(t + 1) & 1][b0 + cbn][h0 + hgrp * 2] = pkt;
            } else {
                float2 rr;
                rr.x = (hsum[0] + ov[0] * t0) * (1.0f / T_);
                rr.y = (hsum[1] + ov[1] * t1) * (1.0f / T_);
                *(float2*)(out + (size_t)(b0 + cbn) * H_ + h0 + hgrp * 2) = rr;
            }
        }

        if (t < T_ - 1) {
            // prefetch next step's xproj BEFORE the barrier (latency hidden)
            {
                const float* xb = g_xproj
                    + (((size_t)g * T_ + (t + 1)) * B_ + b0) * H_ + h0;
#pragma unroll
                for (int j = 0; j < 2; j++) {
                    int n0c = (2 * p + j) * 8 + ecol;
                    xv[j][0] = xb[(size_t)(n0c)     * H_ + erow];
                    xv[j][1] = xb[(size_t)(n0c + 1) * H_ + erow];
                    xv[j][2] = xb[(size_t)(n0c)     * H_ + erow + 8];
                    xv[j][3] = xb[(size_t)(n0c + 1) * H_ + erow + 8];
                }
            }
            __syncthreads();               // act reuse + h stores done
            if (tid == 0) {
                unsigned target = s0 + (unsigned)(t + 1);
                __threadfence();
                unsigned arr = atomicAdd(&g_cnt[nt][0], 1u);
                if (arr == GRPSZ - 1) {
                    g_cnt[nt][0] = 0;
                    asm volatile("st.release.gpu.u32 [%0], %1;"
                                 :: "l"(&g_sns[nt][0]), "r"(target) : "memory");
                } else {
                    unsigned v;
                    do {
                        asm volatile("ld.acquire.gpu.u32 %0, [%1];"
                                     : "=r"(v) : "l"(&g_sns[nt][0]) : "memory");
                    } while ((int)(v - target) < 0);
                }
            }
            __syncthreads();
        }
    }
}

// ---------------------------------------------------------------------------
extern "C" void kernel_launch(void* const* d_in, const int* in_sizes, int n_in,
                              void* d_out, int out_size) {
    const float* x  = (const float*)d_in[0];
    const float* Wz = (const float*)d_in[1];
    const float* Ws = (const float*)d_in[2];
    const float* Wf = (const float*)d_in[3];
    const float* Wo = (const float*)d_in[4];
    const float* Rz = (const float*)d_in[5];
    const float* Rs = (const float*)d_in[6];
    const float* Rf = (const float*)d_in[7];
    const float* Ro = (const float*)d_in[8];
    const float* bz = (const float*)d_in[9];
    const float* bs = (const float*)d_in[10];
    const float* bf = (const float*)d_in[11];
    const float* bo = (const float*)d_in[12];

    const int smem_bytes = 131072 + 32768 + 64 * 33 * 4;   // ~168.5KB
    cudaFuncSetAttribute(lstm_recur,
                         cudaFuncAttributeMaxDynamicSharedMemorySize, smem_bytes);

    lstm_proj<<<dim3((B_ * T_) / 64, (4 * H_) / 64), 128>>>(
        x, Wz, Ws, Wf, Wo, bz, bs, bf, bo);
    lstm_recur<<<RCTAS, 256, smem_bytes>>>(Rz, Rs, Rf, Ro, (float*)d_out);
}

// round 15
// speedup vs baseline: 1.0713x; 1.0713x over previous
#include <cuda_runtime.h>
#include <cuda_fp16.h>
#include <cstdint>
#include <cmath>

#define B_ 128
#define T_ 512
#define I_ 256
#define H_ 512
#define RCTAS 128
#define GRPSZ 32          // CTAs per barrier group (one per b-slice)

// ---- static device scratch ----
__device__ float    g_xproj[(size_t)4 * T_ * B_ * H_];  // [g][t][b][h]
__device__ __half   g_hH[2][B_][H_];                    // h fp16 [buf][b][h]
__device__ unsigned g_cnt[4][32];                       // per-group barrier counter
__device__ unsigned g_sns[4][32];                       // per-group barrier sense (persists)

// ---- packed fp32x2 (projection kernel) ----
__device__ __forceinline__ void fma2(unsigned long long& d,
                                     unsigned long long a,
                                     unsigned long long b) {
    asm("fma.rn.f32x2 %0, %1, %2, %0;" : "+l"(d) : "l"(a), "l"(b));
}
__device__ __forceinline__ float lo32(unsigned long long v) {
    return __uint_as_float((unsigned)(v & 0xffffffffull));
}
__device__ __forceinline__ float hi32(unsigned long long v) {
    return __uint_as_float((unsigned)(v >> 32));
}
__device__ __forceinline__ float rcpa(float x) {
    float r;
    asm("rcp.approx.f32 %0, %1;" : "=f"(r) : "f"(x));
    return r;
}
// rational tanh p/q (Eigen coefficients, float-accurate)
__device__ __forceinline__ void tanh_pq(float x, float& p, float& q) {
    x = fminf(fmaxf(x, -7.90531110763549805f), 7.90531110763549805f);
    float x2 = x * x;
    float pp = fmaf(x2, -2.76076847742355e-16f, 2.00018790482477e-13f);
    pp = fmaf(pp, x2, -8.60467152213735e-11f);
    pp = fmaf(pp, x2, 5.12229709037114e-08f);
    pp = fmaf(pp, x2, 1.48572235717979e-05f);
    pp = fmaf(pp, x2, 6.37261928875436e-04f);
    pp = fmaf(pp, x2, 4.89352455891786e-03f);
    p = pp * x;
    float qq = fmaf(x2, 1.19825839466702e-06f, 1.18534705686654e-04f);
    qq = fmaf(qq, x2, 2.26843463243900e-03f);
    q = fmaf(qq, x2, 4.89352518554385e-03f);
}
__device__ __forceinline__ void div4(const float* p, const float* q, float* o) {
    float q01 = q[0] * q[1], q23 = q[2] * q[3];
    float r   = rcpa(q01 * q23);
    float r01 = q23 * r, r23 = q01 * r;
    o[0] = p[0] * (q[1] * r01);
    o[1] = p[1] * (q[0] * r01);
    o[2] = p[2] * (q[3] * r23);
    o[3] = p[3] * (q[2] * r23);
}

// ---- warp MMA helpers ----
__device__ __forceinline__ void ldsm4(uint32_t& r0, uint32_t& r1, uint32_t& r2,
                                      uint32_t& r3, uint32_t addr) {
    asm volatile("ldmatrix.sync.aligned.m8n8.x4.shared.b16 {%0,%1,%2,%3}, [%4];"
                 : "=r"(r0), "=r"(r1), "=r"(r2), "=r"(r3) : "r"(addr));
}
__device__ __forceinline__ void ldsm2(uint32_t& r0, uint32_t& r1, uint32_t addr) {
    asm volatile("ldmatrix.sync.aligned.m8n8.x2.shared.b16 {%0,%1}, [%2];"
                 : "=r"(r0), "=r"(r1) : "r"(addr));
}
__device__ __forceinline__ void mma16816(float* c, uint32_t a0, uint32_t a1,
                                         uint32_t a2, uint32_t a3,
                                         uint32_t b0, uint32_t b1) {
    asm volatile(
        "mma.sync.aligned.m16n8k16.row.col.f32.f16.f16.f32 "
        "{%0,%1,%2,%3}, {%4,%5,%6,%7}, {%8,%9}, {%0,%1,%2,%3};"
        : "+f"(c[0]), "+f"(c[1]), "+f"(c[2]), "+f"(c[3])
        : "r"(a0), "r"(a1), "r"(a2), "r"(a3), "r"(b0), "r"(b1));
}

// ---------------------------------------------------------------------------
// projection GEMM (proven R6-R13): g_xproj[g][t][b][h] = x.W_g^T + b_g
// ---------------------------------------------------------------------------
__global__ __launch_bounds__(128) void lstm_proj(
    const float* __restrict__ x,
    const float* __restrict__ Wz, const float* __restrict__ Ws,
    const float* __restrict__ Wf, const float* __restrict__ Wo,
    const float* __restrict__ bz, const float* __restrict__ bs,
    const float* __restrict__ bf, const float* __restrict__ bo)
{
    __shared__ __align__(16) float2 As2[32][64];
    __shared__ __align__(16) float  Bs[32][64];

    const int tid = threadIdx.x;
    const int r0  = blockIdx.x * 64;
    const int n0  = blockIdx.y * 64;
    const int g   = n0 >> 9;
    const int h0  = n0 & 511;

    const float* W    = (g == 0) ? Wz : (g == 1) ? Ws : (g == 2) ? Wf : Wo;
    const float* bias = (g == 0) ? bz : (g == 1) ? bs : (g == 2) ? bf : bo;

    const int tn = tid & 7;
    const int tm = tid >> 3;
    const int lm = tid & 63;
    const int qb = (tid >> 6) * 4;
    const float* xr = x + (size_t)(r0 + lm) * I_;
    const float* wr = W + (size_t)(h0 + lm) * I_;

    unsigned long long acc[4][4];
#pragma unroll
    for (int i = 0; i < 4; i++)
#pragma unroll
        for (int j = 0; j < 4; j++) acc[i][j] = 0ull;

    float4 pa[4], pw[4];
#pragma unroll
    for (int i = 0; i < 4; i++) {
        pa[i] = *(const float4*)(xr + (qb + i) * 4);
        pw[i] = *(const float4*)(wr + (qb + i) * 4);
    }

    for (int kt = 0; kt < I_ / 32; kt++) {
#pragma unroll
        for (int i = 0; i < 4; i++) {
            int q = qb + i;
            As2[q * 4 + 0][lm] = make_float2(pa[i].x, pa[i].x);
            As2[q * 4 + 1][lm] = make_float2(pa[i].y, pa[i].y);
            As2[q * 4 + 2][lm] = make_float2(pa[i].z, pa[i].z);
            As2[q * 4 + 3][lm] = make_float2(pa[i].w, pa[i].w);
            Bs[q * 4 + 0][lm] = pw[i].x;
            Bs[q * 4 + 1][lm] = pw[i].y;
            Bs[q * 4 + 2][lm] = pw[i].z;
            Bs[q * 4 + 3][lm] = pw[i].w;
        }
        __syncthreads();
        if (kt + 1 < I_ / 32) {
            int k0 = (kt + 1) * 32;
#pragma unroll
            for (int i = 0; i < 4; i++) {
                pa[i] = *(const float4*)(xr + k0 + (qb + i) * 4);
                pw[i] = *(const float4*)(wr + k0 + (qb + i) * 4);
            }
        }
#pragma unroll
        for (int kk = 0; kk < 32; kk++) {
            ulonglong2 a01 = *(const ulonglong2*)&As2[kk][tm * 4];
            ulonglong2 a23 = *(const ulonglong2*)&As2[kk][tm * 4 + 2];
            ulonglong2 b01 = *(const ulonglong2*)&Bs[kk][tn * 8];
            ulonglong2 b23 = *(const ulonglong2*)&Bs[kk][tn * 8 + 4];
            fma2(acc[0][0], a01.x, b01.x); fma2(acc[0][1], a01.x, b01.y);
            fma2(acc[0][2], a01.x, b23.x); fma2(acc[0][3], a01.x, b23.y);
            fma2(acc[1][0], a01.y, b01.x); fma2(acc[1][1], a01.y, b01.y);
            fma2(acc[1][2], a01.y, b23.x); fma2(acc[1][3], a01.y, b23.y);
            fma2(acc[2][0], a23.x, b01.x); fma2(acc[2][1], a23.x, b01.y);
            fma2(acc[2][2], a23.x, b23.x); fma2(acc[2][3], a23.x, b23.y);
            fma2(acc[3][0], a23.y, b01.x); fma2(acc[3][1], a23.y, b01.y);
            fma2(acc[3][2], a23.y, b23.x); fma2(acc[3][3], a23.y, b23.y);
        }
        __syncthreads();
    }

    float bv[8];
#pragma unroll
    for (int j = 0; j < 8; j++) bv[j] = bias[h0 + tn * 8 + j];
#pragma unroll
    for (int i = 0; i < 4; i++) {
        int r  = r0 + tm * 4 + i;
        int bb = r >> 9;
        int tt = r & 511;
        float* orow = g_xproj + (((size_t)g * T_ + tt) * B_ + bb) * H_ + h0 + tn * 8;
#pragma unroll
        for (int jp = 0; jp < 4; jp++) {
            float2 v = make_float2(lo32(acc[i][jp]) + bv[jp * 2],
                                   hi32(acc[i][jp]) + bv[jp * 2 + 1]);
            *(float2*)(orow + jp * 2) = v;
        }
    }
}

// ---------------------------------------------------------------------------
// persistent HMMA recurrence v3. 128 CTAs x 128 thr (4 warps).
// CTA tile: M=64 (16h x 4g, gate-paired rows) x N=32 batch x K=512.
// Warp (hg, np): m32 = tile0{z,s}x8h + tile1{f,o}x8h, n16. The mma fragment
// layout hands each thread z,s,f,o for its 4 (h,b) cells -> combine is fully
// warp-local: no act smem, no extra syncthreads.
// A = R hi/lo f16 resident 128KB; B = h f16 staged per step 32KB.
// ---------------------------------------------------------------------------
__global__ __launch_bounds__(128, 1) void lstm_recur(
    const float* __restrict__ Rz, const float* __restrict__ Rs_,
    const float* __restrict__ Rf, const float* __restrict__ Ro,
    float* __restrict__ out)
{
    extern __shared__ char sm[];
    char* smA = sm;                       // 131072 B (rows 0..127 x 1024B)
    char* smB = sm + 131072;              // 32768 B  (32 n-rows x 1024B)
    const uint32_t smem_base = (uint32_t)__cvta_generic_to_shared(sm);
    const uint32_t SM_A = smem_base;
    const uint32_t SM_B = smem_base + 131072;

    const int tid = threadIdx.x;
    const int w   = tid >> 5;
    const int l   = tid & 31;
    const int hg  = w >> 1;            // h-half of the 16-h tile
    const int np  = w & 1;             // n-half (16 batches)
    const int mt  = blockIdx.x >> 2;   // 32 h-tiles
    const int nt  = blockIdx.x & 3;    // 4 b-tiles
    const int h0  = mt * 16;
    const int b0  = nt * 32;

    // barrier sense (self-relative, persists; race-free winner-reset scheme)
    unsigned s0 = 0;
    if (tid == 0) s0 = *(volatile unsigned*)&g_sns[nt][0];

    // ---- setup: A rows; row m: hg=m>>5, tile=(m>>4)&1, gate=(m>>3)&3,
    //      h_local = (m>>5)*8 + (m&7). hi rows 0..63, lo rows 64..127. ----
    {
        const int m  = tid & 63;
        const int kh = (tid >> 6) * 256;    // k half
        const int gg = (m >> 3) & 3;
        const int hl = ((m >> 5) << 3) | (m & 7);
        const float* Rp = ((gg == 0) ? Rz : (gg == 1) ? Rs_ : (gg == 2) ? Rf : Ro)
                        + (size_t)(h0 + hl) * H_ + kh;
        char* rowHi = smA + m * 1024;
        char* rowLo = smA + (64 + m) * 1024;
        const int sx = m & 7;
#pragma unroll 8
        for (int k = 0; k < 256; k += 2) {
            float2 v = *(const float2*)(Rp + k);
            __half hv0 = __float2half(v.x);
            __half hv1 = __float2half(v.y);
            float r0 = v.x - __half2float(hv0);
            float r1 = v.y - __half2float(hv1);
            uint32_t hi = (uint32_t)__half_as_ushort(hv0)
                        | ((uint32_t)__half_as_ushort(hv1) << 16);
            uint32_t lo = (uint32_t)__half_as_ushort(__float2half(r0))
                        | ((uint32_t)__half_as_ushort(__float2half(r1)) << 16);
            int byte  = (kh + k) * 2;
            int chunk = byte >> 4;
            int off   = ((chunk ^ sx) << 4) + (byte & 15);
            *(uint32_t*)(rowHi + off) = hi;
            *(uint32_t*)(rowLo + off) = lo;
        }
    }
    __syncthreads();

    // ldmatrix addressing
    const uint32_t aB0  = SM_A + (uint32_t)(hg * 32 + (l & 15)) * 1024u;  // tile0 hi
    const uint32_t aB1  = aB0 + 16 * 1024u;                               // tile1 hi
    const uint32_t aL0  = aB0 + 64 * 1024u;                               // tile0 lo
    const uint32_t aL1  = aB1 + 64 * 1024u;                               // tile1 lo
    const uint32_t aXor = (uint32_t)(l & 7);
    const uint32_t aKl  = (uint32_t)(l >> 4);
    const uint32_t bXr  = (uint32_t)(l & 7);
    const uint32_t bKl  = (uint32_t)((l >> 3) & 1);
    const uint32_t bBase = SM_B + (uint32_t)(np * 16 + (l & 7)) * 1024u;

    // cell identity: h = h0 + hg*8 + (l>>2); 4 n's
    const int hl  = hg * 8 + (l >> 2);
    const int hgl = h0 + hl;
    int nn[4];
    nn[0] = np * 16 + (l & 3) * 2;
    nn[1] = nn[0] + 1;
    nn[2] = nn[0] + 8;
    nn[3] = nn[0] + 9;

    float creg[4] = {0, 0, 0, 0}, hsum[4] = {0, 0, 0, 0};

    // B staging role: 16 x 16B chunks per thread
    const int srow = tid >> 2;          // 0..31
    const int sc0  = (tid & 3) * 16;
    const int sx2  = srow & 7;

    // preload xproj for t=0: 16 values (4 gates x 4 cells)
    float xz[4], xs[4], xf[4], xo[4];
    {
#pragma unroll
        for (int i = 0; i < 4; i++) {
            size_t off = (size_t)(b0 + nn[i]) * H_ + hgl;
            xz[i] = g_xproj[((size_t)0 * T_ + 0) * B_ * H_ + off];
            xs[i] = g_xproj[((size_t)1 * T_ + 0) * B_ * H_ + off];
            xf[i] = g_xproj[((size_t)2 * T_ + 0) * B_ * H_ + off];
            xo[i] = g_xproj[((size_t)3 * T_ + 0) * B_ * H_ + off];
        }
    }

    for (int t = 0; t < T_; t++) {
        float a00[4] = {0, 0, 0, 0};   // tile0 x j0: z(nA),z(nB),s(nA),s(nB)
        float a01[4] = {0, 0, 0, 0};   // tile0 x j1: z(nC),z(nD),s(nC),s(nD)
        float a10[4] = {0, 0, 0, 0};   // tile1 x j0: f,f,o,o
        float a11[4] = {0, 0, 0, 0};   // tile1 x j1

        if (t > 0) {
            // ---- stage B: g_hH[t&1][b0+row][k] -> swizzled smem ----
            {
                const char* gsrc = (const char*)&g_hH[t & 1][b0 + srow][0];
                char* sdst = smB + srow * 1024;
#pragma unroll
                for (int i = 0; i < 16; i++) {
                    int c = sc0 + i;
                    uint4 v = *(const uint4*)(gsrc + c * 16);
                    *(uint4*)(sdst + ((c ^ sx2) << 4)) = v;
                }
            }
            __syncthreads();

            // ---- GEMM: warp m32 x n16 x K512 (hi + lo) ----
#pragma unroll 4
            for (int ks = 0; ks < 32; ks++) {
                uint32_t aOff = ((((uint32_t)(ks * 2) + aKl) ^ aXor) << 4);
                uint32_t h00, h01, h02, h03, h10, h11, h12, h13;
                uint32_t l00, l01, l02, l03, l10, l11, l12, l13;
                ldsm4(h00, h01, h02, h03, aB0 + aOff);
                ldsm4(h10, h11, h12, h13, aB1 + aOff);
                ldsm4(l00, l01, l02, l03, aL0 + aOff);
                ldsm4(l10, l11, l12, l13, aL1 + aOff);
                uint32_t bOff = ((((uint32_t)(ks * 2) + bKl) ^ bXr) << 4);
                uint32_t b00, b01, b10, b11;
                ldsm2(b00, b01, bBase + bOff);
                ldsm2(b10, b11, bBase + 8192u + bOff);
                mma16816(a00, h00, h01, h02, h03, b00, b01);
                mma16816(a01, h00, h01, h02, h03, b10, b11);
                mma16816(a10, h10, h11, h12, h13, b00, b01);
                mma16816(a11, h10, h11, h12, h13, b10, b11);
                mma16816(a00, l00, l01, l02, l03, b00, b01);
                mma16816(a01, l00, l01, l02, l03, b10, b11);
                mma16816(a10, l10, l11, l12, l13, b00, b01);
                mma16816(a11, l10, l11, l12, l13, b10, b11);
            }
        }

        // ---- fully local combine: 4 cells (hgl, b0+nn[i]) ----
        {
            // gather pre-acts per gate (cell order nA,nB,nC,nD)
            float pz[4] = {a00[0] + xz[0], a00[1] + xz[1], a01[0] + xz[2], a01[1] + xz[3]};
            float ps[4] = {a00[2] + xs[0], a00[3] + xs[1], a01[2] + xs[2], a01[3] + xs[3]};
            float pf[4] = {a10[0] + xf[0], a10[1] + xf[1], a11[0] + xf[2], a11[1] + xf[3]};
            float po[4] = {a10[2] + xo[0], a10[3] + xo[1], a11[2] + xo[2], a11[3] + xo[3]};

            float pn[4], qn[4];
            float zv[4], sv[4], fv[4], ov[4];
#pragma unroll
            for (int i = 0; i < 4; i++) tanh_pq(pz[i], pn[i], qn[i]);
            div4(pn, qn, zv);
#pragma unroll
            for (int i = 0; i < 4; i++) tanh_pq(ps[i] * 0.5f, pn[i], qn[i]);
            div4(pn, qn, sv);
#pragma unroll
            for (int i = 0; i < 4; i++) sv[i] = fmaf(sv[i], 0.5f, 0.5f);
#pragma unroll
            for (int i = 0; i < 4; i++) tanh_pq(pf[i] * 0.5f, pn[i], qn[i]);
            div4(pn, qn, fv);
#pragma unroll
            for (int i = 0; i < 4; i++) fv[i] = fmaf(fv[i], 0.5f, 0.5f);
#pragma unroll
            for (int i = 0; i < 4; i++) tanh_pq(po[i] * 0.5f, pn[i], qn[i]);
            div4(pn, qn, ov);
#pragma unroll
            for (int i = 0; i < 4; i++) ov[i] = fmaf(ov[i], 0.5f, 0.5f);

            float tc[4];
#pragma unroll
            for (int i = 0; i < 4; i++) {
                float c = fmaf(sv[i], zv[i], fv[i] * creg[i]);
                creg[i] = c;
                tanh_pq(c, pn[i], qn[i]);
            }
            div4(pn, qn, tc);

            if (t < T_ - 1) {
                ushort* hbuf = (ushort*)&g_hH[(t + 1) & 1][0][0];
#pragma unroll
                for (int i = 0; i < 4; i++) {
                    float hn = ov[i] * tc[i];
                    hsum[i] += hn;
                    hbuf[(size_t)(b0 + nn[i]) * H_ + hgl] =
                        __half_as_ushort(__float2half(hn));
                }
            } else {
#pragma unroll
                for (int i = 0; i < 4; i++)
                    out[(size_t)(b0 + nn[i]) * H_ + hgl] =
                        (hsum[i] + ov[i] * tc[i]) * (1.0f / (float)T_);
            }
        }

        if (t < T_ - 1) {
            // prefetch next step's xproj BEFORE the barrier (latency hidden)
            {
#pragma unroll
                for (int i = 0; i < 4; i++) {
                    size_t off = (size_t)(b0 + nn[i]) * H_ + hgl;
                    size_t tb  = (size_t)(t + 1) * B_ * H_;
                    xz[i] = g_xproj[((size_t)0 * T_) * B_ * H_ + tb + off];
                    xs[i] = g_xproj[((size_t)1 * T_) * B_ * H_ + tb + off];
                    xf[i] = g_xproj[((size_t)2 * T_) * B_ * H_ + tb + off];
                    xo[i] = g_xproj[((size_t)3 * T_) * B_ * H_ + tb + off];
                }
            }
            __syncthreads();               // all h stores issued
            if (tid == 0) {
                unsigned target = s0 + (unsigned)(t + 1);
                __threadfence();
                unsigned arr = atomicAdd(&g_cnt[nt][0], 1u);
                if (arr == GRPSZ - 1) {
                    g_cnt[nt][0] = 0;
                    asm volatile("st.release.gpu.u32 [%0], %1;"
                                 :: "l"(&g_sns[nt][0]), "r"(target) : "memory");
                } else {
                    unsigned v;
                    do {
                        asm volatile("ld.acquire.gpu.u32 %0, [%1];"
                                     : "=r"(v) : "l"(&g_sns[nt][0]) : "memory");
                    } while ((int)(v - target) < 0);
                }
            }
            __syncthreads();
        }
    }
}

// ---------------------------------------------------------------------------
extern "C" void kernel_launch(void* const* d_in, const int* in_sizes, int n_in,
                              void* d_out, int out_size) {
    const float* x  = (const float*)d_in[0];
    const float* Wz = (const float*)d_in[1];
    const float* Ws = (const float*)d_in[2];
    const float* Wf = (const float*)d_in[3];
    const float* Wo = (const float*)d_in[4];
    const float* Rz = (const float*)d_in[5];
    const float* Rs = (const float*)d_in[6];
    const float* Rf = (const float*)d_in[7];
    const float* Ro = (const float*)d_in[8];
    const float* bz = (const float*)d_in[9];
    const float* bs = (const float*)d_in[10];
    const float* bf = (const float*)d_in[11];
    const float* bo = (const float*)d_in[12];

    const int smem_bytes = 131072 + 32768 + 64;   // ~160KB (no act buffer)
    cudaFuncSetAttribute(lstm_recur,
                         cudaFuncAttributeMaxDynamicSharedMemorySize, smem_bytes);

    lstm_proj<<<dim3((B_ * T_) / 64, (4 * H_) / 64), 128>>>(
        x, Wz, Ws, Wf, Wo, bz, bs, bf, bo);
    lstm_recur<<<RCTAS, 128, smem_bytes>>>(Rz, Rs, Rf, Ro, (float*)d_out);
}

// round 16
// speedup vs baseline: 1.6243x; 1.5163x over previous
#include <cuda_runtime.h>
#include <cuda_fp16.h>
#include <cstdint>
#include <cmath>

#define B_ 128
#define T_ 512
#define I_ 256
#define H_ 512
#define RCTAS 128
#define GRPSZ 32          // CTAs per barrier group (one per b-slice)

// ---- static device scratch ----
__device__ float    g_xproj[(size_t)4 * T_ * B_ * H_];  // [g][t][b][h]
__device__ __half   g_xh[(size_t)B_ * T_ * I_];         // x as f16, [bt][k]
__device__ __half   g_whl[(size_t)4 * H_ * 2 * I_];     // W hi/lo interleaved rows
__device__ __half   g_hH[2][B_][H_];                    // h fp16 [buf][b][h]
__device__ unsigned g_cnt[4][32];                       // per-group barrier counter
__device__ unsigned g_sns[4][32];                       // per-group barrier sense (persists)

__device__ __forceinline__ float rcpa(float x) {
    float r;
    asm("rcp.approx.f32 %0, %1;" : "=f"(r) : "f"(x));
    return r;
}
// rational tanh p/q (Eigen coefficients, float-accurate)
__device__ __forceinline__ void tanh_pq(float x, float& p, float& q) {
    x = fminf(fmaxf(x, -7.90531110763549805f), 7.90531110763549805f);
    float x2 = x * x;
    float pp = fmaf(x2, -2.76076847742355e-16f, 2.00018790482477e-13f);
    pp = fmaf(pp, x2, -8.60467152213735e-11f);
    pp = fmaf(pp, x2, 5.12229709037114e-08f);
    pp = fmaf(pp, x2, 1.48572235717979e-05f);
    pp = fmaf(pp, x2, 6.37261928875436e-04f);
    pp = fmaf(pp, x2, 4.89352455891786e-03f);
    p = pp * x;
    float qq = fmaf(x2, 1.19825839466702e-06f, 1.18534705686654e-04f);
    qq = fmaf(qq, x2, 2.26843463243900e-03f);
    q = fmaf(qq, x2, 4.89352518554385e-03f);
}
__device__ __forceinline__ void div4(const float* p, const float* q, float* o) {
    float q01 = q[0] * q[1], q23 = q[2] * q[3];
    float r   = rcpa(q01 * q23);
    float r01 = q23 * r, r23 = q01 * r;
    o[0] = p[0] * (q[1] * r01);
    o[1] = p[1] * (q[0] * r01);
    o[2] = p[2] * (q[3] * r23);
    o[3] = p[3] * (q[2] * r23);
}

// ---- warp MMA helpers ----
__device__ __forceinline__ void ldsm4(uint32_t& r0, uint32_t& r1, uint32_t& r2,
                                      uint32_t& r3, uint32_t addr) {
    asm volatile("ldmatrix.sync.aligned.m8n8.x4.shared.b16 {%0,%1,%2,%3}, [%4];"
                 : "=r"(r0), "=r"(r1), "=r"(r2), "=r"(r3) : "r"(addr));
}
__device__ __forceinline__ void ldsm2(uint32_t& r0, uint32_t& r1, uint32_t addr) {
    asm volatile("ldmatrix.sync.aligned.m8n8.x2.shared.b16 {%0,%1}, [%2];"
                 : "=r"(r0), "=r"(r1) : "r"(addr));
}
__device__ __forceinline__ void mma16816(float* c, uint32_t a0, uint32_t a1,
                                         uint32_t a2, uint32_t a3,
                                         uint32_t b0, uint32_t b1) {
    asm volatile(
        "mma.sync.aligned.m16n8k16.row.col.f32.f16.f16.f32 "
        "{%0,%1,%2,%3}, {%4,%5,%6,%7}, {%8,%9}, {%0,%1,%2,%3};"
        : "+f"(c[0]), "+f"(c[1]), "+f"(c[2]), "+f"(c[3])
        : "r"(a0), "r"(a1), "r"(a2), "r"(a3), "r"(b0), "r"(b1));
}

// ---------------------------------------------------------------------------
// prep: x -> f16 ; W -> hi/lo f16 interleaved rows [gh*2 + islo][k]
// ---------------------------------------------------------------------------
__global__ __launch_bounds__(256) void prep_x(const float* __restrict__ x) {
    size_t idx = ((size_t)blockIdx.x * 256 + threadIdx.x) * 8;
    float4 v0 = *(const float4*)(x + idx);
    float4 v1 = *(const float4*)(x + idx + 4);
    __half2 h0 = __floats2half2_rn(v0.x, v0.y);
    __half2 h1 = __floats2half2_rn(v0.z, v0.w);
    __half2 h2 = __floats2half2_rn(v1.x, v1.y);
    __half2 h3 = __floats2half2_rn(v1.z, v1.w);
    uint4 pkt;
    pkt.x = *(uint32_t*)&h0; pkt.y = *(uint32_t*)&h1;
    pkt.z = *(uint32_t*)&h2; pkt.w = *(uint32_t*)&h3;
    *(uint4*)(&g_xh[idx]) = pkt;
}

__global__ __launch_bounds__(64) void prep_w(
    const float* __restrict__ Wz, const float* __restrict__ Ws,
    const float* __restrict__ Wf, const float* __restrict__ Wo)
{
    int gh = blockIdx.x;               // 0..2047
    int g  = gh >> 9;
    const float* W = ((g == 0) ? Wz : (g == 1) ? Ws : (g == 2) ? Wf : Wo);
    const float* src = W + (size_t)(gh & 511) * I_;
    __half* dhi = &g_whl[(size_t)(gh * 2 + 0) * I_];
    __half* dlo = &g_whl[(size_t)(gh * 2 + 1) * I_];
    for (int k = threadIdx.x * 4; k < I_; k += 64 * 4) {
        float4 v = *(const float4*)(src + k);
        __half h0 = __float2half(v.x), h1 = __float2half(v.y);
        __half h2 = __float2half(v.z), h3 = __float2half(v.w);
        __half l0 = __float2half(v.x - __half2float(h0));
        __half l1 = __float2half(v.y - __half2float(h1));
        __half l2 = __float2half(v.z - __half2float(h2));
        __half l3 = __float2half(v.w - __half2float(h3));
        dhi[k] = h0; dhi[k+1] = h1; dhi[k+2] = h2; dhi[k+3] = h3;
        dlo[k] = l0; dlo[k+1] = l1; dlo[k+2] = l2; dlo[k+3] = l3;
    }
}

// ---------------------------------------------------------------------------
// HMMA projection: C[bt][gh] = x_f16 . (W_hi + W_lo)^T + bias
// CTA tile: M=128 bt x N=64 Wrows (=32 h, hi/lo pairs) x K=256 (fully resident).
// 4 warps, 2x2 split: warp m64 x n32. Epilogue sums adjacent col pairs.
// ---------------------------------------------------------------------------
__global__ __launch_bounds__(128) void lstm_proj_mma(
    const float* __restrict__ bz, const float* __restrict__ bs,
    const float* __restrict__ bf, const float* __restrict__ bo)
{
    extern __shared__ char sm[];
    const uint32_t smem_base = (uint32_t)__cvta_generic_to_shared(sm);
    const uint32_t SM_X = smem_base;            // 128 rows x 512B = 64KB
    const uint32_t SM_W = smem_base + 65536;    // 64 rows x 512B  = 32KB

    const int tid = threadIdx.x;
    const int w   = tid >> 5;
    const int l   = tid & 31;
    const int wm  = w >> 1;            // m-half (64 rows)
    const int wn  = w & 1;             // n-half (32 rows)
    const int r0  = blockIdx.x * 128;  // bt base
    const int nt  = blockIdx.y;        // 0..63 (64-row W blocks)

    // ---- stage x tile: row = tid, 32 chunks of 16B, swizzled ----
    {
        const __half* xr = &g_xh[(size_t)(r0 + tid) * I_];
        char* dst = sm + tid * 512;
        const int sx = tid & 7;
#pragma unroll 8
        for (int c = 0; c < 32; c++) {
            uint4 v = *(const uint4*)(xr + c * 8);
            *(uint4*)(dst + ((c ^ sx) << 4)) = v;
        }
    }
    // ---- stage W tile: 64 rows, 2 threads per row ----
    {
        const int row = tid & 63;
        const int h2  = tid >> 6;
        const __half* wr = &g_whl[(size_t)(nt * 64 + row) * I_ + h2 * 128];
        char* dst = sm + 65536 + row * 512;
        const int sx = row & 7;
#pragma unroll 8
        for (int i = 0; i < 16; i++) {
            int c = h2 * 16 + i;
            uint4 v = *(const uint4*)(wr + i * 8);
            *(uint4*)(dst + ((c ^ sx) << 4)) = v;
        }
    }
    __syncthreads();

    // ldmatrix addressing
    uint32_t aBase[4], aXor[4];
#pragma unroll
    for (int i = 0; i < 4; i++) {
        uint32_t row = (uint32_t)(wm * 64 + 16 * i + (l & 15));
        aBase[i] = SM_X + row * 512u;
        aXor[i]  = row & 7;
    }
    const uint32_t aKl = (uint32_t)(l >> 4);
    uint32_t bBase[4], bXor[4];
#pragma unroll
    for (int j = 0; j < 4; j++) {
        uint32_t row = (uint32_t)(wn * 32 + 8 * j + (l & 7));
        bBase[j] = SM_W + row * 512u;
        bXor[j]  = row & 7;
    }
    const uint32_t bKl = (uint32_t)((l >> 3) & 1);

    float acc[4][4][4];
#pragma unroll
    for (int i = 0; i < 4; i++)
#pragma unroll
        for (int j = 0; j < 4; j++)
#pragma unroll
            for (int q = 0; q < 4; q++) acc[i][j][q] = 0.0f;

    // ---- GEMM sweep: K=256, 16 k-steps ----
#pragma unroll 2
    for (int ks = 0; ks < 16; ks++) {
        uint32_t a[4][4];
#pragma unroll
        for (int i = 0; i < 4; i++) {
            uint32_t c = ((uint32_t)(ks * 2) + aKl) ^ aXor[i];
            ldsm4(a[i][0], a[i][1], a[i][2], a[i][3], aBase[i] + (c << 4));
        }
        uint32_t b0[4], b1[4];
#pragma unroll
        for (int j = 0; j < 4; j++) {
            uint32_t c = ((uint32_t)(ks * 2) + bKl) ^ bXor[j];
            ldsm2(b0[j], b1[j], bBase[j] + (c << 4));
        }
#pragma unroll
        for (int i = 0; i < 4; i++)
#pragma unroll
            for (int j = 0; j < 4; j++)
                mma16816(acc[i][j], a[i][0], a[i][1], a[i][2], a[i][3],
                         b0[j], b1[j]);
    }

    // ---- epilogue: sum hi/lo col pairs, add bias, scatter to g_xproj ----
    const int gh0 = nt * 32;
    const int g   = gh0 >> 9;
    const int hb  = gh0 & 511;
    const float* bias = ((g == 0) ? bz : (g == 1) ? bs : (g == 2) ? bf : bo);
    float bv[4];
    int   hc[4];
#pragma unroll
    for (int j = 0; j < 4; j++) {
        hc[j] = hb + wn * 16 + 4 * j + (l & 3);
        bv[j] = bias[hc[j]];
    }
#pragma unroll
    for (int i = 0; i < 4; i++) {
        int r  = r0 + wm * 64 + 16 * i + (l >> 2);
        int bA = r >> 9,       tA = r & 511;
        int bB = (r + 8) >> 9, tB = (r + 8) & 511;
#pragma unroll
        for (int j = 0; j < 4; j++) {
            float v0 = acc[i][j][0] + acc[i][j][1] + bv[j];
            float v1 = acc[i][j][2] + acc[i][j][3] + bv[j];
            g_xproj[(((size_t)g * T_ + tA) * B_ + bA) * H_ + hc[j]] = v0;
            g_xproj[(((size_t)g * T_ + tB) * B_ + bB) * H_ + hc[j]] = v1;
        }
    }
}

// ---------------------------------------------------------------------------
// persistent HMMA recurrence (R14 winner, verbatim). 128 CTAs x 128 thr.
// ---------------------------------------------------------------------------
__global__ __launch_bounds__(128, 1) void lstm_recur(
    const float* __restrict__ Rz, const float* __restrict__ Rs_,
    const float* __restrict__ Rf, const float* __restrict__ Ro,
    float* __restrict__ out)
{
    extern __shared__ char sm[];
    char* smA = sm;                       // 131072 B (rows 0..127 x 1024B)
    char* smB = sm + 131072;              // 32768 B  (32 n-rows x 1024B)
    const uint32_t smem_base = (uint32_t)__cvta_generic_to_shared(sm);
    const uint32_t SM_A = smem_base;
    const uint32_t SM_B = smem_base + 131072;

    const int tid = threadIdx.x;
    const int w   = tid >> 5;
    const int l   = tid & 31;
    const int hg  = w >> 1;
    const int np  = w & 1;
    const int mt  = blockIdx.x >> 2;
    const int nt  = blockIdx.x & 3;
    const int h0  = mt * 16;
    const int b0  = nt * 32;

    unsigned s0 = 0;
    if (tid == 0) s0 = *(volatile unsigned*)&g_sns[nt][0];

    {
        const int m  = tid & 63;
        const int kh = (tid >> 6) * 256;
        const int gg = (m >> 3) & 3;
        const int hl = ((m >> 5) << 3) | (m & 7);
        const float* Rp = ((gg == 0) ? Rz : (gg == 1) ? Rs_ : (gg == 2) ? Rf : Ro)
                        + (size_t)(h0 + hl) * H_ + kh;
        char* rowHi = smA + m * 1024;
        char* rowLo = smA + (64 + m) * 1024;
        const int sx = m & 7;
#pragma unroll 8
        for (int k = 0; k < 256; k += 2) {
            float2 v = *(const float2*)(Rp + k);
            __half hv0 = __float2half(v.x);
            __half hv1 = __float2half(v.y);
            float r0 = v.x - __half2float(hv0);
            float r1 = v.y - __half2float(hv1);
            uint32_t hi = (uint32_t)__half_as_ushort(hv0)
                        | ((uint32_t)__half_as_ushort(hv1) << 16);
            uint32_t lo = (uint32_t)__half_as_ushort(__float2half(r0))
                        | ((uint32_t)__half_as_ushort(__float2half(r1)) << 16);
            int byte  = (kh + k) * 2;
            int chunk = byte >> 4;
            int off   = ((chunk ^ sx) << 4) + (byte & 15);
            *(uint32_t*)(rowHi + off) = hi;
            *(uint32_t*)(rowLo + off) = lo;
        }
    }
    __syncthreads();

    const uint32_t aB0  = SM_A + (uint32_t)(hg * 32 + (l & 15)) * 1024u;
    const uint32_t aB1  = aB0 + 16 * 1024u;
    const uint32_t aL0  = aB0 + 64 * 1024u;
    const uint32_t aL1  = aB1 + 64 * 1024u;
    const uint32_t aXor = (uint32_t)(l & 7);
    const uint32_t aKl  = (uint32_t)(l >> 4);
    const uint32_t bXr  = (uint32_t)(l & 7);
    const uint32_t bKl  = (uint32_t)((l >> 3) & 1);
    const uint32_t bBase = SM_B + (uint32_t)(np * 16 + (l & 7)) * 1024u;

    const int hl  = hg * 8 + (l >> 2);
    const int hgl = h0 + hl;
    int nn[4];
    nn[0] = np * 16 + (l & 3) * 2;
    nn[1] = nn[0] + 1;
    nn[2] = nn[0] + 8;
    nn[3] = nn[0] + 9;

    float creg[4] = {0, 0, 0, 0}, hsum[4] = {0, 0, 0, 0};

    const int srow = tid >> 2;
    const int sc0  = (tid & 3) * 16;
    const int sx2  = srow & 7;

    float xz[4], xs[4], xf[4], xo[4];
    {
#pragma unroll
        for (int i = 0; i < 4; i++) {
            size_t off = (size_t)(b0 + nn[i]) * H_ + hgl;
            xz[i] = g_xproj[((size_t)0 * T_ + 0) * B_ * H_ + off];
            xs[i] = g_xproj[((size_t)1 * T_ + 0) * B_ * H_ + off];
            xf[i] = g_xproj[((size_t)2 * T_ + 0) * B_ * H_ + off];
            xo[i] = g_xproj[((size_t)3 * T_ + 0) * B_ * H_ + off];
        }
    }

    for (int t = 0; t < T_; t++) {
        float a00[4] = {0, 0, 0, 0};
        float a01[4] = {0, 0, 0, 0};
        float a10[4] = {0, 0, 0, 0};
        float a11[4] = {0, 0, 0, 0};

        if (t > 0) {
            {
                const char* gsrc = (const char*)&g_hH[t & 1][b0 + srow][0];
                char* sdst = smB + srow * 1024;
#pragma unroll
                for (int i = 0; i < 16; i++) {
                    int c = sc0 + i;
                    uint4 v = *(const uint4*)(gsrc + c * 16);
                    *(uint4*)(sdst + ((c ^ sx2) << 4)) = v;
                }
            }
            __syncthreads();

#pragma unroll 4
            for (int ks = 0; ks < 32; ks++) {
                uint32_t aOff = ((((uint32_t)(ks * 2) + aKl) ^ aXor) << 4);
                uint32_t h00, h01, h02, h03, h10, h11, h12, h13;
                uint32_t l00, l01, l02, l03, l10, l11, l12, l13;
                ldsm4(h00, h01, h02, h03, aB0 + aOff);
                ldsm4(h10, h11, h12, h13, aB1 + aOff);
                ldsm4(l00, l01, l02, l03, aL0 + aOff);
                ldsm4(l10, l11, l12, l13, aL1 + aOff);
                uint32_t bOff = ((((uint32_t)(ks * 2) + bKl) ^ bXr) << 4);
                uint32_t b00, b01, b10, b11;
                ldsm2(b00, b01, bBase + bOff);
                ldsm2(b10, b11, bBase + 8192u + bOff);
                mma16816(a00, h00, h01, h02, h03, b00, b01);
                mma16816(a01, h00, h01, h02, h03, b10, b11);
                mma16816(a10, h10, h11, h12, h13, b00, b01);
                mma16816(a11, h10, h11, h12, h13, b10, b11);
                mma16816(a00, l00, l01, l02, l03, b00, b01);
                mma16816(a01, l00, l01, l02, l03, b10, b11);
                mma16816(a10, l10, l11, l12, l13, b00, b01);
                mma16816(a11, l10, l11, l12, l13, b10, b11);
            }
        }

        {
            float pz[4] = {a00[0] + xz[0], a00[1] + xz[1], a01[0] + xz[2], a01[1] + xz[3]};
            float ps[4] = {a00[2] + xs[0], a00[3] + xs[1], a01[2] + xs[2], a01[3] + xs[3]};
            float pf[4] = {a10[0] + xf[0], a10[1] + xf[1], a11[0] + xf[2], a11[1] + xf[3]};
            float po[4] = {a10[2] + xo[0], a10[3] + xo[1], a11[2] + xo[2], a11[3] + xo[3]};

            float pn[4], qn[4];
            float zv[4], sv[4], fv[4], ov[4];
#pragma unroll
            for (int i = 0; i < 4; i++) tanh_pq(pz[i], pn[i], qn[i]);
            div4(pn, qn, zv);
#pragma unroll
            for (int i = 0; i < 4; i++) tanh_pq(ps[i] * 0.5f, pn[i], qn[i]);
            div4(pn, qn, sv);
#pragma unroll
            for (int i = 0; i < 4; i++) sv[i] = fmaf(sv[i], 0.5f, 0.5f);
#pragma unroll
            for (int i = 0; i < 4; i++) tanh_pq(pf[i] * 0.5f, pn[i], qn[i]);
            div4(pn, qn, fv);
#pragma unroll
            for (int i = 0; i < 4; i++) fv[i] = fmaf(fv[i], 0.5f, 0.5f);
#pragma unroll
            for (int i = 0; i < 4; i++) tanh_pq(po[i] * 0.5f, pn[i], qn[i]);
            div4(pn, qn, ov);
#pragma unroll
            for (int i = 0; i < 4; i++) ov[i] = fmaf(ov[i], 0.5f, 0.5f);

            float tc[4];
#pragma unroll
            for (int i = 0; i < 4; i++) {
                float c = fmaf(sv[i], zv[i], fv[i] * creg[i]);
                creg[i] = c;
                tanh_pq(c, pn[i], qn[i]);
            }
            div4(pn, qn, tc);

            if (t < T_ - 1) {
                ushort* hbuf = (ushort*)&g_hH[(t + 1) & 1][0][0];
#pragma unroll
                for (int i = 0; i < 4; i++) {
                    float hn = ov[i] * tc[i];
                    hsum[i] += hn;
                    hbuf[(size_t)(b0 + nn[i]) * H_ + hgl] =
                        __half_as_ushort(__float2half(hn));
                }
            } else {
#pragma unroll
                for (int i = 0; i < 4; i++)
                    out[(size_t)(b0 + nn[i]) * H_ + hgl] =
                        (hsum[i] + ov[i] * tc[i]) * (1.0f / (float)T_);
            }
        }

        if (t < T_ - 1) {
            {
#pragma unroll
                for (int i = 0; i < 4; i++) {
                    size_t off = (size_t)(b0 + nn[i]) * H_ + hgl;
                    size_t tb  = (size_t)(t + 1) * B_ * H_;
                    xz[i] = g_xproj[((size_t)0 * T_) * B_ * H_ + tb + off];
                    xs[i] = g_xproj[((size_t)1 * T_) * B_ * H_ + tb + off];
                    xf[i] = g_xproj[((size_t)2 * T_) * B_ * H_ + tb + off];
                    xo[i] = g_xproj[((size_t)3 * T_) * B_ * H_ + tb + off];
                }
            }
            __syncthreads();
            if (tid == 0) {
                unsigned target = s0 + (unsigned)(t + 1);
                __threadfence();
                unsigned arr = atomicAdd(&g_cnt[nt][0], 1u);
                if (arr == GRPSZ - 1) {
                    g_cnt[nt][0] = 0;
                    asm volatile("st.release.gpu.u32 [%0], %1;"
                                 :: "l"(&g_sns[nt][0]), "r"(target) : "memory");
                } else {
                    unsigned v;
                    do {
                        asm volatile("ld.acquire.gpu.u32 %0, [%1];"
                                     : "=r"(v) : "l"(&g_sns[nt][0]) : "memory");
                    } while ((int)(v - target) < 0);
                }
            }
            __syncthreads();
        }
    }
}

// ---------------------------------------------------------------------------
extern "C" void kernel_launch(void* const* d_in, const int* in_sizes, int n_in,
                              void* d_out, int out_size) {
    const float* x  = (const float*)d_in[0];
    const float* Wz = (const float*)d_in[1];
    const float* Ws = (const float*)d_in[2];
    const float* Wf = (const float*)d_in[3];
    const float* Wo = (const float*)d_in[4];
    const float* Rz = (const float*)d_in[5];
    const float* Rs = (const float*)d_in[6];
    const float* Rf = (const float*)d_in[7];
    const float* Ro = (const float*)d_in[8];
    const float* bz = (const float*)d_in[9];
    const float* bs = (const float*)d_in[10];
    const float* bf = (const float*)d_in[11];
    const float* bo = (const float*)d_in[12];

    const int proj_smem  = 65536 + 32768;          // 96KB
    const int recur_smem = 131072 + 32768 + 64;    // ~160KB
    cudaFuncSetAttribute(lstm_proj_mma,
                         cudaFuncAttributeMaxDynamicSharedMemorySize, proj_smem);
    cudaFuncSetAttribute(lstm_recur,
                         cudaFuncAttributeMaxDynamicSharedMemorySize, recur_smem);

    prep_x<<<(B_ * T_ * I_) / (256 * 8), 256>>>(x);
    prep_w<<<4 * H_, 64>>>(Wz, Ws, Wf, Wo);
    lstm_proj_mma<<<dim3((B_ * T_) / 128, (4 * H_ * 2) / 64), 128, proj_smem>>>(
        bz, bs, bf, bo);
    lstm_recur<<<RCTAS, 128, recur_smem>>>(Rz, Rs, Rf, Ro, (float*)d_out);
}